// round 17
// baseline (speedup 1.0000x reference)
#include <cuda_runtime.h>
#include <cstdint>

#define OUT_F 28672
#define IN_F  8192
#define ROW_BYTES 16384            // int32-widened qweight row: 4096 * 4 B
#define RPB 16                     // rows per block
#define CHUNK_B 1024               // bytes per row per stage (proven best)
#define NCHUNK (ROW_BYTES / CHUNK_B)   // 16
#define STAGE_B (RPB * CHUNK_B)        // 16 KB per stage

// qweight is int32 (harness-widened uint8): each element is a byte value
// 0..255 = two 4-bit codes (lo nibble -> even column, hi nibble -> odd).
//
// Occupancy round: all 77-79%-DRAM configs were register-file-bound at
// ~24 warps/SM (79 regs/thread). Here each 1 KB row-chunk is consumed by TWO
// warps (one per 512 B half): warp w -> row group w&3 (4 rows), half w>>2.
// Per-warp register set shrinks (enforced <=51 via launch bounds) and
// 8 warps/block x 5-6 blocks/SM = 40-48 warps/SM. TMA staging identical to
// R11 (16-row stages, parallel refill, double buffer). Each row gets two
// warp-partials, merged once in smem at the end.

__device__ __forceinline__ uint32_t smem_u32(const void* p) {
    return (uint32_t)__cvta_generic_to_shared(p);
}
__device__ __forceinline__ void mbar_init(uint32_t mbar, uint32_t count) {
    asm volatile("mbarrier.init.shared.b64 [%0], %1;" :: "r"(mbar), "r"(count) : "memory");
}
__device__ __forceinline__ void mbar_expect_tx(uint32_t mbar, uint32_t bytes) {
    asm volatile("mbarrier.arrive.expect_tx.shared.b64 _, [%0], %1;"
                 :: "r"(mbar), "r"(bytes) : "memory");
}
__device__ __forceinline__ void bulk_g2s(uint32_t dst, const void* src,
                                         uint32_t bytes, uint32_t mbar) {
    asm volatile(
        "cp.async.bulk.shared::cluster.global.mbarrier::complete_tx::bytes "
        "[%0], [%1], %2, [%3];"
        :: "r"(dst), "l"(src), "r"(bytes), "r"(mbar) : "memory");
}
__device__ __forceinline__ void mbar_wait(uint32_t mbar, uint32_t parity) {
    uint32_t done;
    asm volatile(
        "{\n\t.reg .pred p;\n\t"
        "mbarrier.try_wait.parity.acquire.cta.shared::cta.b64 p, [%1], %2;\n\t"
        "selp.b32 %0, 1, 0, p;\n\t}"
        : "=r"(done) : "r"(mbar), "r"(parity) : "memory");
    if (!done) {
        asm volatile(
            "{\n\t.reg .pred P1;\n\t"
            "WL_%=:\n\t"
            "mbarrier.try_wait.parity.acquire.cta.shared::cta.b64 P1, [%0], %1, 0x989680;\n\t"
            "@P1 bra.uni WD_%=;\n\t"
            "bra.uni WL_%=;\n\t"
            "WD_%=:\n\t}"
            :: "r"(mbar), "r"(parity) : "memory");
    }
}

__global__ __launch_bounds__(256, 5)
void q3_matvec_kernel(const float* __restrict__ x,
                      const int* __restrict__ qw,
                      const float* __restrict__ kv,
                      const float* __restrict__ bias,
                      float* __restrict__ y)
{
    __shared__ alignas(128) uint8_t s_buf[2][STAGE_B];   // 2 x 16 KB
    __shared__ float s_lut[RPB * 16];                    // 16 row-LUTs (1 KB)
    __shared__ float s_part[RPB][2];                     // per-row half-partials
    __shared__ alignas(8) uint64_t s_mbar[2];

    const int t = threadIdx.x;
    const int w = t >> 5;
    const int l = t & 31;
    const int g = w & 3;            // row group (4 rows)
    const int hsel = w >> 2;        // which 512 B half of each 1 KB chunk
    const int rbase = blockIdx.x * RPB;

    // Stage 256 LUT floats (one per thread).
    s_lut[t] = kv[rbase * 16 + t];

    const uint32_t mb0 = smem_u32(&s_mbar[0]);
    const uint32_t mb1 = smem_u32(&s_mbar[1]);
    const uint32_t bu0 = smem_u32(&s_buf[0][0]);
    const uint32_t bu1 = smem_u32(&s_buf[1][0]);

    if (t == 0) { mbar_init(mb0, 1); mbar_init(mb1, 1); }
    __syncthreads();

    const char* gq = (const char*)qw + (size_t)rbase * ROW_BYTES;

    // Prologue: fill both stages (chunks 0 and 1), 16 parallel issuers.
    if (t == 0) { mbar_expect_tx(mb0, STAGE_B); mbar_expect_tx(mb1, STAGE_B); }
    if (t < RPB) {
        __syncwarp(0x0000ffffu);
        const char* rowp = gq + (size_t)t * ROW_BYTES;
        bulk_g2s(bu0 + t * CHUNK_B, rowp,           CHUNK_B, mb0);
        bulk_g2s(bu1 + t * CHUNK_B, rowp + CHUNK_B, CHUNK_B, mb1);
    }

    const float* lut0 = s_lut + (g << 2) * 16;
    const float4* xp = reinterpret_cast<const float4*>(x);

    float a00 = 0.f, a01 = 0.f;
    float a10 = 0.f, a11 = 0.f;
    float a20 = 0.f, a21 = 0.f;
    float a30 = 0.f, a31 = 0.f;

    #pragma unroll 1
    for (int c = 0; c < NCHUNK; c++) {
        const int st = c & 1;
        const uint32_t mb = st ? mb1 : mb0;
        mbar_wait(mb, (c >> 1) & 1);

        // This warp: rows 4g..4g+3, bytes [hsel*512, +512) of the 1 KB chunk.
        // Lane l -> columns c*512 + hsel*256 + 8l .. +7.
        const float4 xa = xp[(c << 7) + (hsel << 6) + (l << 1)];
        const float4 xb = xp[(c << 7) + (hsel << 6) + (l << 1) + 1];

        const uint8_t* buf = s_buf[st] + ((g << 2) * CHUNK_B) + (hsel << 9) + (l << 4);
        const uint4 q0 = *reinterpret_cast<const uint4*>(buf);
        const uint4 q1 = *reinterpret_cast<const uint4*>(buf + CHUNK_B);
        const uint4 q2 = *reinterpret_cast<const uint4*>(buf + 2 * CHUNK_B);
        const uint4 q3 = *reinterpret_cast<const uint4*>(buf + 3 * CHUNK_B);

        // v <= 255 so (v >> 4) is already a clean code (no mask).
        #define DO_ROW(Q, LUT, A0, A1)                        \
            A0 = fmaf((LUT)[(Q).x & 15u], xa.x, A0);          \
            A1 = fmaf((LUT)[(Q).x >> 4],  xa.y, A1);          \
            A0 = fmaf((LUT)[(Q).y & 15u], xa.z, A0);          \
            A1 = fmaf((LUT)[(Q).y >> 4],  xa.w, A1);          \
            A0 = fmaf((LUT)[(Q).z & 15u], xb.x, A0);          \
            A1 = fmaf((LUT)[(Q).z >> 4],  xb.y, A1);          \
            A0 = fmaf((LUT)[(Q).w & 15u], xb.z, A0);          \
            A1 = fmaf((LUT)[(Q).w >> 4],  xb.w, A1);

        DO_ROW(q0, lut0,      a00, a01)
        DO_ROW(q1, lut0 + 16, a10, a11)
        DO_ROW(q2, lut0 + 32, a20, a21)
        DO_ROW(q3, lut0 + 48, a30, a31)
        #undef DO_ROW

        __syncthreads();   // stage st fully consumed by all 8 warps

        if (c + 2 < NCHUNK) {
            if (t == 0) mbar_expect_tx(mb, STAGE_B);
            if (t < RPB) {
                __syncwarp(0x0000ffffu);
                const uint32_t bu = st ? bu1 : bu0;
                bulk_g2s(bu + t * CHUNK_B,
                         gq + (size_t)t * ROW_BYTES + (size_t)(c + 2) * CHUNK_B,
                         CHUNK_B, mb);
            }
        }
    }

    // Per-warp reduction of its 4 half-row partials, then merge the two
    // halves per row through smem.
    float r0 = a00 + a01;
    float r1 = a10 + a11;
    float r2 = a20 + a21;
    float r3 = a30 + a31;
    #pragma unroll
    for (int s = 16; s > 0; s >>= 1) {
        r0 += __shfl_xor_sync(0xffffffffu, r0, s);
        r1 += __shfl_xor_sync(0xffffffffu, r1, s);
        r2 += __shfl_xor_sync(0xffffffffu, r2, s);
        r3 += __shfl_xor_sync(0xffffffffu, r3, s);
    }
    if (l == 0) {
        s_part[(g << 2) + 0][hsel] = r0;
        s_part[(g << 2) + 1][hsel] = r1;
        s_part[(g << 2) + 2][hsel] = r2;
        s_part[(g << 2) + 3][hsel] = r3;
    }
    __syncthreads();

    if (t < RPB)
        y[rbase + t] = s_part[t][0] + s_part[t][1] + bias[rbase + t];
}

extern "C" void kernel_launch(void* const* d_in, const int* in_sizes, int n_in,
                              void* d_out, int out_size)
{
    const float* x    = (const float*)d_in[0];
    const int*   qw   = (const int*)d_in[1];
    const float* kv   = (const float*)d_in[2];
    const float* bias = (const float*)d_in[3];
    float*       y    = (float*)d_out;

    dim3 grid(OUT_F / RPB);   // 1792 blocks of 8 warps
    dim3 block(256);
    q3_matvec_kernel<<<grid, block>>>(x, qw, kv, bias, y);
}